// round 15
// baseline (speedup 1.0000x reference)
#include <cuda_runtime.h>

// TransformDomainInterpolator, GB300 (sm_103a). Merged shuffle-FFT kernel.
//
// Math: fc = M/2 keeps ALL 2048 DFT bins -> exact 2x bandlimited interp:
//   out[2m]   = x[m]
//   out[2m+1] = IDFT2048( DFT2048(x)[k] * w[k] )/2048,
//     w[k] = e^{+i*pi*k/2048} (k<1024), -e^{+i*pi*k/2048} (k>=1024)
// Time: out[t] = lerp(H2, H11, clamp((t-2)/9, 0, 1)).
//
// One 256-thread block per batch. Both row FFTs run sequentially with the
// R14-verified shuffle pipeline (bits m=[b10..b0], thread=b7..b0, regs=
// b10b9b8; 2 smem transposes, 9 shfl/reg stages, 4 barriers per row).
// Row0 odd-values parked in smem dbuf; all 14 output symbols written
// directly (t=0..2 overlapped with row1's FFT). No scratch, no 2nd kernel.

#define MM 2048
#define NSYM 14
#define PADN 2176
#define PIDX(i) ((i) + ((i) >> 4))

static __device__ __forceinline__ float2 cmul(float2 a, float2 b) {
    return make_float2(fmaf(a.x, b.x, -a.y * b.y), fmaf(a.x, b.y, a.y * b.x));
}
static __device__ __forceinline__ float2 cadd(float2 a, float2 b) {
    return make_float2(a.x + b.x, a.y + b.y);
}
static __device__ __forceinline__ float2 csub(float2 a, float2 b) {
    return make_float2(a.x - b.x, a.y - b.y);
}
static __device__ __forceinline__ float2 shflx(float2 v, int mask) {
    return make_float2(__shfl_xor_sync(0xffffffffu, v.x, mask),
                       __shfl_xor_sync(0xffffffffu, v.y, mask));
}

// 3 forward DIF register stages on reg bits (hi,mid,lo) of x[8].
static __device__ __forceinline__ void fwd3(float2* __restrict__ x,
    float2 wa0, float2 wa1, float2 wa2, float2 wa3, float2 wb0, float2 wc)
{
    { float2 u=x[0], v=x[4]; x[0]=cadd(u,v); x[4]=cmul(csub(u,v), wa0); }
    { float2 u=x[1], v=x[5]; x[1]=cadd(u,v); x[5]=cmul(csub(u,v), wa1); }
    { float2 u=x[2], v=x[6]; x[2]=cadd(u,v); x[6]=cmul(csub(u,v), wa2); }
    { float2 u=x[3], v=x[7]; x[3]=cadd(u,v); x[7]=cmul(csub(u,v), wa3); }
    float2 wb1 = make_float2(wb0.y, -wb0.x);          // -i * wb0
    #pragma unroll
    for (int o = 0; o < 8; o += 4) {
        float2 u=x[o],   v=x[o+2]; x[o]=cadd(u,v);   x[o+2]=cmul(csub(u,v), wb0);
        u=x[o+1]; v=x[o+3];        x[o+1]=cadd(u,v); x[o+3]=cmul(csub(u,v), wb1);
    }
    #pragma unroll
    for (int g = 0; g < 4; ++g) {
        float2 u=x[2*g], v=x[2*g+1];
        x[2*g]=cadd(u,v); x[2*g+1]=cmul(csub(u,v), wc);
    }
}

// 3 inverse DIT register stages (lo,mid,hi), conjugate twiddles.
static __device__ __forceinline__ void inv3(float2* __restrict__ x,
    float2 wa0, float2 wa1, float2 wa2, float2 wa3, float2 wb0, float2 wc)
{
    float2 cwc = make_float2(wc.x, -wc.y);
    #pragma unroll
    for (int g = 0; g < 4; ++g) {
        float2 t = cmul(x[2*g+1], cwc);
        float2 u = x[2*g];
        x[2*g]=cadd(u,t); x[2*g+1]=csub(u,t);
    }
    float2 cwb0 = make_float2(wb0.x, -wb0.y);
    float2 cwb1 = make_float2(wb0.y,  wb0.x);         // conj(-i*wb0)
    #pragma unroll
    for (int o = 0; o < 8; o += 4) {
        float2 t = cmul(x[o+2], cwb0); float2 u = x[o];
        x[o]=cadd(u,t); x[o+2]=csub(u,t);
        t = cmul(x[o+3], cwb1); u = x[o+1];
        x[o+1]=cadd(u,t); x[o+3]=csub(u,t);
    }
    { float2 t=cmul(x[4], make_float2(wa0.x,-wa0.y)); float2 u=x[0]; x[0]=cadd(u,t); x[4]=csub(u,t); }
    { float2 t=cmul(x[5], make_float2(wa1.x,-wa1.y)); float2 u=x[1]; x[1]=cadd(u,t); x[5]=csub(u,t); }
    { float2 t=cmul(x[6], make_float2(wa2.x,-wa2.y)); float2 u=x[2]; x[2]=cadd(u,t); x[6]=csub(u,t); }
    { float2 t=cmul(x[7], make_float2(wa3.x,-wa3.y)); float2 u=x[3]; x[3]=cadd(u,t); x[7]=csub(u,t); }
}

// Full fwd+pointwise+inv pass for one row; result in x[] (natural order,
// m = q8 + 256*r). First __syncthreads also guards ys reuse across calls.
static __device__ __forceinline__ void fft_row(
    const float* __restrict__ rbr, const float* __restrict__ ibr,
    float2* __restrict__ ys, const float2* __restrict__ tw,
    int q8, int lane, int w3, float2* __restrict__ x)
{
    #pragma unroll
    for (int r = 0; r < 8; ++r) {
        int m = q8 + 256 * r;
        x[r] = make_float2(rbr[m], ibr[m]);
    }
    __syncthreads();   // tw ready (call 1) / prior ys reads done (call 2)

    // fwd stages 10,9,8 on regs (b10b9b8)
    fwd3(x, tw[q8], tw[q8+256], tw[q8+512], tw[q8+768], tw[2*q8], tw[4*q8]);

    // transpose: regs (b10b9b8) -> (b7b6b5)
    #pragma unroll
    for (int r = 0; r < 8; ++r) ys[PIDX(q8 + 256 * r)] = x[r];
    __syncthreads();
    #pragma unroll
    for (int r = 0; r < 8; ++r) x[r] = ys[PIDX(w3 * 256 + r * 32 + lane)];

    // fwd stages 7,6,5 on regs (b7b6b5)
    fwd3(x, tw[8*lane], tw[8*lane+256], tw[8*lane+512], tw[8*lane+768],
         tw[16*lane], tw[32*lane]);

    // fwd stages 4..1: shfl_xor on lane bits
    #pragma unroll
    for (int s = 4; s >= 1; --s) {
        int mask = 1 << s;
        float2 w = tw[(lane & (mask - 1)) << (10 - s)];
        bool bot = (lane & mask) != 0;
        #pragma unroll
        for (int r = 0; r < 8; ++r) {
            float2 o = shflx(x[r], mask);
            if (bot) x[r] = cmul(csub(o, x[r]), w);
            else     x[r] = cadd(x[r], o);
        }
    }

    // MID: fwd s0 (w=1) + pointwise + inv s0 (w=1), via shfl mask 1
    {
        bool odd = (lane & 1) != 0;
        #pragma unroll
        for (int r = 0; r < 8; ++r) {
            float2 o = shflx(x[r], 1);
            x[r] = odd ? csub(o, x[r]) : cadd(x[r], o);
        }
        int kbase = 64 * (int)(__brev((unsigned)lane) >> 27)
                  + (int)(__brev((unsigned)w3) >> 29);
        float sv, cv;
        sincospif((float)kbase * (1.0f / 2048.0f), &sv, &cv);
        float ss = odd ? -(1.0f / 2048.0f) : (1.0f / 2048.0f);
        float2 baseW = make_float2(cv * ss, sv * ss);
        const float2 CPW[8] = {                // e^{i*pi*brev3(r)/256}
            {1.000000000f, 0.000000000f},
            {0.998795456f, 0.049067674f},
            {0.999698819f, 0.024541229f},
            {0.997290457f, 0.073564564f},
            {0.999924702f, 0.012271538f},
            {0.998118113f, 0.061320736f},
            {0.999322385f, 0.036807223f},
            {0.996312612f, 0.085797312f}};
        #pragma unroll
        for (int r = 0; r < 8; ++r) x[r] = cmul(x[r], cmul(baseW, CPW[r]));
        #pragma unroll
        for (int r = 0; r < 8; ++r) {
            float2 o = shflx(x[r], 1);
            x[r] = odd ? csub(o, x[r]) : cadd(x[r], o);
        }
    }

    // inv stages 1..4: shfl_xor, conjugate twiddles
    #pragma unroll
    for (int s = 1; s <= 4; ++s) {
        int mask = 1 << s;
        float2 w0 = tw[(lane & (mask - 1)) << (10 - s)];
        float2 cw = make_float2(w0.x, -w0.y);
        bool bot = (lane & mask) != 0;
        #pragma unroll
        for (int r = 0; r < 8; ++r) {
            float2 o = shflx(x[r], mask);
            if (bot) x[r] = csub(o, cmul(x[r], cw));
            else     x[r] = cadd(x[r], cmul(o, cw));
        }
    }

    // inv stages 5,6,7 on regs (b7b6b5)
    inv3(x, tw[8*lane], tw[8*lane+256], tw[8*lane+512], tw[8*lane+768],
         tw[16*lane], tw[32*lane]);

    // transpose back: regs -> (b10b9b8)
    __syncthreads();
    #pragma unroll
    for (int r = 0; r < 8; ++r) ys[PIDX(w3 * 256 + r * 32 + lane)] = x[r];
    __syncthreads();
    #pragma unroll
    for (int r = 0; r < 8; ++r) x[r] = ys[PIDX(q8 + 256 * r)];

    // inv stages 8,9,10 on regs -> natural m = q8 + 256*r
    inv3(x, tw[q8], tw[q8+256], tw[q8+512], tw[q8+768], tw[2*q8], tw[4*q8]);
}

// MODE 0: real-only f32 output. MODE 1: interleaved complex-as-f32 output.
template <int MODE>
__global__ void __launch_bounds__(256) tdi_kernel(
    const float* __restrict__ re,
    const float* __restrict__ im,
    void* __restrict__ outv)
{
    __shared__ float2 tw[1024];      // tw[t] = e^{-i*pi*t/1024}
    __shared__ float2 ys[PADN];
    __shared__ float2 dbuf[MM];      // row0 odd-values

    const int b    = blockIdx.x;
    const int q8   = threadIdx.x;    // b7..b0
    const int lane = q8 & 31;
    const int w3   = q8 >> 5;

    for (int t = q8; t < 1024; t += 256) {
        float s, c;
        sincospif(-(float)t * (1.0f / 1024.0f), &s, &c);
        tw[t] = make_float2(c, s);
    }

    const float* rb = re + (size_t)b * 4096;
    const float* ib = im + (size_t)b * 4096;

    float2 x[8];

    // ===== Row 0 (symbol 2) =====
    fft_row(rb, ib, ys, tw, q8, lane, w3, x);

    // Park d2, write t=0,1,2 (a=0 -> pure row0). Overlaps row1's FFT.
    #pragma unroll
    for (int r = 0; r < 8; ++r) {
        int m = q8 + 256 * r;
        dbuf[m] = x[r];
        if (MODE == 0) {
            float2 v = make_float2(rb[m], x[r].x);
            #pragma unroll
            for (int tt = 0; tt < 3; ++tt)
                ((float2*)outv)[((size_t)b * NSYM + tt) * MM + m] = v;
        } else {
            float4 v = make_float4(rb[m], ib[m], x[r].x, x[r].y);
            #pragma unroll
            for (int tt = 0; tt < 3; ++tt)
                ((float4*)outv)[((size_t)b * NSYM + tt) * MM + m] = v;
        }
    }

    // ===== Row 1 (symbol 11) ===== (fft_row's first sync guards ys reuse;
    // dbuf reads below are same-thread slots, no extra barrier needed)
    fft_row(rb + MM, ib + MM, ys, tw, q8, lane, w3, x);

    #pragma unroll
    for (int r = 0; r < 8; ++r) {
        int m = q8 + 256 * r;
        if (MODE == 0) {
            float e11 = rb[MM + m], d11 = x[r].x;
            float2 v1 = make_float2(e11, d11);
            #pragma unroll
            for (int tt = 11; tt < 14; ++tt)
                ((float2*)outv)[((size_t)b * NSYM + tt) * MM + m] = v1;
            float e2 = rb[m], d2 = dbuf[m].x;
            float de = e11 - e2, dd = d11 - d2;
            #pragma unroll
            for (int t = 3; t <= 10; ++t) {
                float a = (float)(t - 2) * (1.0f / 9.0f);
                float2 v = make_float2(fmaf(a, de, e2), fmaf(a, dd, d2));
                ((float2*)outv)[((size_t)b * NSYM + t) * MM + m] = v;
            }
        } else {
            float2 e11 = make_float2(rb[MM + m], ib[MM + m]);
            float2 d11 = x[r];
            float4 v1 = make_float4(e11.x, e11.y, d11.x, d11.y);
            #pragma unroll
            for (int tt = 11; tt < 14; ++tt)
                ((float4*)outv)[((size_t)b * NSYM + tt) * MM + m] = v1;
            float2 e2 = make_float2(rb[m], ib[m]);
            float2 d2 = dbuf[m];
            float2 de = csub(e11, e2), dd = csub(d11, d2);
            #pragma unroll
            for (int t = 3; t <= 10; ++t) {
                float a = (float)(t - 2) * (1.0f / 9.0f);
                float4 v = make_float4(fmaf(a, de.x, e2.x), fmaf(a, de.y, e2.y),
                                       fmaf(a, dd.x, d2.x), fmaf(a, dd.y, d2.y));
                ((float4*)outv)[((size_t)b * NSYM + t) * MM + m] = v;
            }
        }
    }
}

extern "C" void kernel_launch(void* const* d_in, const int* in_sizes, int n_in,
                              void* d_out, int out_size)
{
    const float* re = (const float*)d_in[0];
    const float* im = (const float*)d_in[1];
    const int B = in_sizes[0] / 4096;
    const long long interleaved = (long long)B * NSYM * 4096 * 2;

    if ((long long)out_size >= interleaved)
        tdi_kernel<1><<<B, 256>>>(re, im, d_out);
    else
        tdi_kernel<0><<<B, 256>>>(re, im, d_out);
}